// round 3
// baseline (speedup 1.0000x reference)
#include <cuda_runtime.h>
#include <cuda_bf16.h>
#include <math.h>

#define MAXN 100000
#define IN_DIM 128
#define HID 64

// Scratch (device globals — allocation-free rule)
__device__ float g_h[(size_t)MAXN * HID];        // last-layer output for GEMM2
__device__ float g_xn[2][(size_t)MAXN * HID];    // ping-pong unit-norm features
__device__ float g_s[2][MAXN];                   // ping-pong norms (+eps)
__device__ int   g_rp[MAXN + 1];                 // CSR row pointer

// ---------------------------------------------------------------------------
// row_ptr via binary search (edge_row sorted ascending)
// ---------------------------------------------------------------------------
__global__ void rowptr_kernel(const int* __restrict__ row, int N, int E) {
    int t = blockIdx.x * blockDim.x + threadIdx.x;
    if (t > N) return;
    int lo = 0, hi = E;
    while (lo < hi) {
        int mid = (lo + hi) >> 1;
        if (row[mid] < t) lo = mid + 1; else hi = mid;
    }
    g_rp[t] = lo;
}

// ---------------------------------------------------------------------------
// GEMM1 (K=128) + ReLU + fused normalization -> g_xn[0], g_s[0]
// Warp computes 4 rows; lane owns 2 output cols. W transposed in smem.
// ---------------------------------------------------------------------------
__global__ void gemm1_norm_kernel(const float* __restrict__ x,
                                  const float* __restrict__ W,
                                  const float* __restrict__ b, int N) {
    __shared__ float Wt[IN_DIM * 64];
    for (int i = threadIdx.x; i < 64 * IN_DIM; i += blockDim.x) {
        int o = i / IN_DIM, k = i % IN_DIM;
        Wt[k * 64 + o] = W[i];
    }
    __syncthreads();

    int warp = threadIdx.x >> 5, lane = threadIdx.x & 31;
    int row0 = (blockIdx.x * 8 + warp) * 4;
    if (row0 >= N) return;

    float xf[4][4];
#pragma unroll
    for (int r = 0; r < 4; r++) {
        int row = min(row0 + r, N - 1);
        const float* xr = x + (size_t)row * IN_DIM;
#pragma unroll
        for (int j = 0; j < 4; j++) xf[r][j] = xr[j * 32 + lane];
    }

    float2 acc[4];
#pragma unroll
    for (int r = 0; r < 4; r++) acc[r] = make_float2(0.f, 0.f);

#pragma unroll
    for (int j = 0; j < 4; j++) {
#pragma unroll
        for (int kk = 0; kk < 32; kk++) {
            float2 w = *(const float2*)&Wt[(j * 32 + kk) * 64 + 2 * lane];
#pragma unroll
            for (int r = 0; r < 4; r++) {
                float bx = __shfl_sync(0xffffffffu, xf[r][j], kk);
                acc[r].x = fmaf(bx, w.x, acc[r].x);
                acc[r].y = fmaf(bx, w.y, acc[r].y);
            }
        }
    }

    float2 bias = ((const float2*)b)[lane];
#pragma unroll
    for (int r = 0; r < 4; r++) {
        int row = row0 + r;
        if (row >= N) break;
        float fx = fmaxf(acc[r].x + bias.x, 0.f);
        float fy = fmaxf(acc[r].y + bias.y, 0.f);
        float p = fx * fx + fy * fy;
        p += __shfl_xor_sync(0xffffffffu, p, 16);
        p += __shfl_xor_sync(0xffffffffu, p, 8);
        p += __shfl_xor_sync(0xffffffffu, p, 4);
        p += __shfl_xor_sync(0xffffffffu, p, 2);
        p += __shfl_xor_sync(0xffffffffu, p, 1);
        float nrm = sqrtf(p) + 1e-12f;
        float inv = 1.0f / nrm;
        ((float2*)g_xn[0])[(size_t)row * 32 + lane] = make_float2(fx * inv, fy * inv);
        if (lane == 0) g_s[0][row] = nrm;
    }
}

// ---------------------------------------------------------------------------
// AGNN propagation + ReLU (+ fused normalize unless LAST).
// Warp per destination node; 4 edges in flight (one per 8-lane quarter);
// lane holds 8 dims. Softmax uses exp(p) directly (p = cosine in [-1,1]).
// ---------------------------------------------------------------------------
template <bool LAST>
__global__ void prop_kernel(const int* __restrict__ colv, int src, int N) {
    int warp = threadIdx.x >> 5;
    int node = blockIdx.x * 8 + warp;
    if (node >= N) return;
    int lane = threadIdx.x & 31;
    int q = lane >> 3, lq = lane & 7;
    int dst = src ^ 1;

    const float4* __restrict__ xn4 = (const float4*)g_xn[src];
    const float*  __restrict__ sv  = g_s[src];
    int beg = g_rp[node], end = g_rp[node + 1];

    if (beg == end) {  // isolated node: out = 0, xn = 0, s = eps
        if (q == 0) {
            float4 z = make_float4(0.f, 0.f, 0.f, 0.f);
            if (LAST) {
                ((float4*)g_h)[node * 16 + lq * 2]     = z;
                ((float4*)g_h)[node * 16 + lq * 2 + 1] = z;
            } else {
                ((float4*)g_xn[dst])[node * 16 + lq * 2]     = z;
                ((float4*)g_xn[dst])[node * 16 + lq * 2 + 1] = z;
                if (lq == 0) g_s[dst][node] = 1e-12f;
            }
        }
        return;
    }

    float4 xa = xn4[node * 16 + lq * 2];
    float4 xb = xn4[node * 16 + lq * 2 + 1];

    float acc[8];
#pragma unroll
    for (int d = 0; d < 8; d++) acc[d] = 0.f;
    float ws = 0.f;

    int total = end - beg;
    int iters = (total + 3) >> 2;
    for (int it = 0; it < iters; it++) {
        int e = beg + q + it * 4;
        bool valid = (e < end);
        int c = valid ? __ldg(&colv[e]) : 0;
        float4 ya = xn4[c * 16 + lq * 2];
        float4 yb = xn4[c * 16 + lq * 2 + 1];
        float s = __ldg(&sv[c]);

        float p = xa.x * ya.x;
        p = fmaf(xa.y, ya.y, p);
        p = fmaf(xa.z, ya.z, p);
        p = fmaf(xa.w, ya.w, p);
        p = fmaf(xb.x, yb.x, p);
        p = fmaf(xb.y, yb.y, p);
        p = fmaf(xb.z, yb.z, p);
        p = fmaf(xb.w, yb.w, p);
        p += __shfl_xor_sync(0xffffffffu, p, 1);
        p += __shfl_xor_sync(0xffffffffu, p, 2);
        p += __shfl_xor_sync(0xffffffffu, p, 4);

        float ev = valid ? __expf(p) : 0.f;  // cosine in [-1,1]: no shift needed
        ws += ev;
        float w = ev * s;                    // fold ||h_c|| back in
        acc[0] = fmaf(w, ya.x, acc[0]);
        acc[1] = fmaf(w, ya.y, acc[1]);
        acc[2] = fmaf(w, ya.z, acc[2]);
        acc[3] = fmaf(w, ya.w, acc[3]);
        acc[4] = fmaf(w, yb.x, acc[4]);
        acc[5] = fmaf(w, yb.y, acc[5]);
        acc[6] = fmaf(w, yb.z, acc[6]);
        acc[7] = fmaf(w, yb.w, acc[7]);
    }

    // merge the 4 quarter-accumulators (butterfly across lanes 8, 16)
    ws += __shfl_xor_sync(0xffffffffu, ws, 8);
    ws += __shfl_xor_sync(0xffffffffu, ws, 16);
#pragma unroll
    for (int d = 0; d < 8; d++) {
        acc[d] += __shfl_xor_sync(0xffffffffu, acc[d], 8);
        acc[d] += __shfl_xor_sync(0xffffffffu, acc[d], 16);
    }

    float inv = 1.0f / fmaxf(ws, 1e-12f);
    float o[8];
#pragma unroll
    for (int d = 0; d < 8; d++) o[d] = fmaxf(acc[d] * inv, 0.f);  // ReLU

    if (LAST) {
        if (q == 0) {
            ((float4*)g_h)[node * 16 + lq * 2]     = make_float4(o[0], o[1], o[2], o[3]);
            ((float4*)g_h)[node * 16 + lq * 2 + 1] = make_float4(o[4], o[5], o[6], o[7]);
        }
    } else {
        // fused normalize for the next layer
        float pp = 0.f;
#pragma unroll
        for (int d = 0; d < 8; d++) pp = fmaf(o[d], o[d], pp);
        pp += __shfl_xor_sync(0xffffffffu, pp, 1);
        pp += __shfl_xor_sync(0xffffffffu, pp, 2);
        pp += __shfl_xor_sync(0xffffffffu, pp, 4);
        float nrm = sqrtf(pp) + 1e-12f;
        float iv = 1.0f / nrm;
        if (q == 0) {
            ((float4*)g_xn[dst])[node * 16 + lq * 2] =
                make_float4(o[0] * iv, o[1] * iv, o[2] * iv, o[3] * iv);
            ((float4*)g_xn[dst])[node * 16 + lq * 2 + 1] =
                make_float4(o[4] * iv, o[5] * iv, o[6] * iv, o[7] * iv);
            if (lq == 0) g_s[dst][node] = nrm;
        }
    }
}

// ---------------------------------------------------------------------------
// GEMM2 (K=64): out = g_h @ W2^T + b2
// ---------------------------------------------------------------------------
__global__ void gemm2_kernel(const float* __restrict__ W,
                             const float* __restrict__ b,
                             float* __restrict__ out, int N) {
    __shared__ float Wt[HID * 64];
    for (int i = threadIdx.x; i < 64 * HID; i += blockDim.x) {
        int o = i / HID, k = i % HID;
        Wt[k * 64 + o] = W[i];
    }
    __syncthreads();

    int warp = threadIdx.x >> 5, lane = threadIdx.x & 31;
    int row0 = (blockIdx.x * 8 + warp) * 4;
    if (row0 >= N) return;

    float xf[4][2];
#pragma unroll
    for (int r = 0; r < 4; r++) {
        int row = min(row0 + r, N - 1);
        const float* xr = g_h + (size_t)row * HID;
#pragma unroll
        for (int j = 0; j < 2; j++) xf[r][j] = xr[j * 32 + lane];
    }

    float2 acc[4];
#pragma unroll
    for (int r = 0; r < 4; r++) acc[r] = make_float2(0.f, 0.f);

#pragma unroll
    for (int j = 0; j < 2; j++) {
#pragma unroll
        for (int kk = 0; kk < 32; kk++) {
            float2 w = *(const float2*)&Wt[(j * 32 + kk) * 64 + 2 * lane];
#pragma unroll
            for (int r = 0; r < 4; r++) {
                float bx = __shfl_sync(0xffffffffu, xf[r][j], kk);
                acc[r].x = fmaf(bx, w.x, acc[r].x);
                acc[r].y = fmaf(bx, w.y, acc[r].y);
            }
        }
    }

    float2 bias = ((const float2*)b)[lane];
#pragma unroll
    for (int r = 0; r < 4; r++) {
        int row = row0 + r;
        if (row < N) {
            ((float2*)out)[(size_t)row * 32 + lane] =
                make_float2(acc[r].x + bias.x, acc[r].y + bias.y);
        }
    }
}

// ---------------------------------------------------------------------------
extern "C" void kernel_launch(void* const* d_in, const int* in_sizes, int n_in,
                              void* d_out, int out_size) {
    const float* x    = (const float*)d_in[0];
    const int*   erow = (const int*)d_in[1];
    const int*   ecol = (const int*)d_in[2];
    const float* W1   = (const float*)d_in[3];
    const float* b1   = (const float*)d_in[4];
    const float* W2   = (const float*)d_in[5];
    const float* b2   = (const float*)d_in[6];

    int N = in_sizes[0] / IN_DIM;
    int E = in_sizes[1];

    rowptr_kernel<<<(N + 1 + 255) / 256, 256>>>(erow, N, E);

    int gemm_blocks = (N + 31) / 32;
    int node_blocks = (N + 7) / 8;

    gemm1_norm_kernel<<<gemm_blocks, 256>>>(x, W1, b1, N);

    prop_kernel<false><<<node_blocks, 256>>>(ecol, 0, N);
    prop_kernel<false><<<node_blocks, 256>>>(ecol, 1, N);
    prop_kernel<false><<<node_blocks, 256>>>(ecol, 0, N);
    prop_kernel<true ><<<node_blocks, 256>>>(ecol, 1, N);

    gemm2_kernel<<<gemm_blocks, 256>>>(W2, b2, (float*)d_out, N);
}

// round 4
// speedup vs baseline: 1.5499x; 1.5499x over previous
#include <cuda_runtime.h>
#include <cuda_bf16.h>
#include <math.h>

#define MAXN 100000
#define IN_DIM 128
#define HID 64

// Scratch (device globals — allocation-free rule)
__device__ float g_h[(size_t)MAXN * HID];        // last-layer output for GEMM2
__device__ float g_xn[2][(size_t)MAXN * HID];    // ping-pong unit-norm features
__device__ float g_s[2][MAXN];                   // ping-pong norms (+eps)
__device__ int   g_rp[MAXN + 1];                 // CSR row pointer

// ---------------------------------------------------------------------------
// row_ptr via binary search (edge_row sorted ascending)
// ---------------------------------------------------------------------------
__global__ void rowptr_kernel(const int* __restrict__ row, int N, int E) {
    int t = blockIdx.x * blockDim.x + threadIdx.x;
    if (t > N) return;
    int lo = 0, hi = E;
    while (lo < hi) {
        int mid = (lo + hi) >> 1;
        if (row[mid] < t) lo = mid + 1; else hi = mid;
    }
    g_rp[t] = lo;
}

// ---------------------------------------------------------------------------
// GEMM1 (K=128) + ReLU + fused normalization -> g_xn[0], g_s[0]
// Warp computes 4 rows; lane owns 2 output cols. W transposed in smem.
// ---------------------------------------------------------------------------
__global__ void gemm1_norm_kernel(const float* __restrict__ x,
                                  const float* __restrict__ W,
                                  const float* __restrict__ b, int N) {
    __shared__ float Wt[IN_DIM * 64];
    for (int i = threadIdx.x; i < 64 * IN_DIM; i += blockDim.x) {
        int o = i / IN_DIM, k = i % IN_DIM;
        Wt[k * 64 + o] = W[i];
    }
    __syncthreads();

    int warp = threadIdx.x >> 5, lane = threadIdx.x & 31;
    int row0 = (blockIdx.x * 8 + warp) * 4;
    if (row0 >= N) return;

    float xf[4][4];
#pragma unroll
    for (int r = 0; r < 4; r++) {
        int row = min(row0 + r, N - 1);
        const float* xr = x + (size_t)row * IN_DIM;
#pragma unroll
        for (int j = 0; j < 4; j++) xf[r][j] = xr[j * 32 + lane];
    }

    float2 acc[4];
#pragma unroll
    for (int r = 0; r < 4; r++) acc[r] = make_float2(0.f, 0.f);

#pragma unroll
    for (int j = 0; j < 4; j++) {
#pragma unroll
        for (int kk = 0; kk < 32; kk++) {
            float2 w = *(const float2*)&Wt[(j * 32 + kk) * 64 + 2 * lane];
#pragma unroll
            for (int r = 0; r < 4; r++) {
                float bx = __shfl_sync(0xffffffffu, xf[r][j], kk);
                acc[r].x = fmaf(bx, w.x, acc[r].x);
                acc[r].y = fmaf(bx, w.y, acc[r].y);
            }
        }
    }

    float2 bias = ((const float2*)b)[lane];
#pragma unroll
    for (int r = 0; r < 4; r++) {
        int row = row0 + r;
        if (row >= N) break;
        float fx = fmaxf(acc[r].x + bias.x, 0.f);
        float fy = fmaxf(acc[r].y + bias.y, 0.f);
        float p = fx * fx + fy * fy;
        p += __shfl_xor_sync(0xffffffffu, p, 16);
        p += __shfl_xor_sync(0xffffffffu, p, 8);
        p += __shfl_xor_sync(0xffffffffu, p, 4);
        p += __shfl_xor_sync(0xffffffffu, p, 2);
        p += __shfl_xor_sync(0xffffffffu, p, 1);
        float nrm = sqrtf(p) + 1e-12f;
        float inv = 1.0f / nrm;
        ((float2*)g_xn[0])[(size_t)row * 32 + lane] = make_float2(fx * inv, fy * inv);
        if (lane == 0) g_s[0][row] = nrm;
    }
}

// ---------------------------------------------------------------------------
// AGNN propagation + ReLU (+ fused normalize unless LAST).
// Warp per destination node; HALF-warp per edge (2 edges in flight).
// Lane l (0..15 within half) loads float4 #l of the source row -> fully
// contiguous 256B per edge, one LDG.128 warp-inst covers both edges.
// Dot reduce = 4 shfls (stay within the 16-lane half).
// Softmax uses exp(p) directly: p = cosine in [-1,1], shift-free is exact.
// ---------------------------------------------------------------------------
template <bool LAST>
__global__ void prop_kernel(const int* __restrict__ colv, int src, int N) {
    int node = blockIdx.x * 8 + (threadIdx.x >> 5);
    if (node >= N) return;
    int lane = threadIdx.x & 31;
    int half = lane >> 4, lh = lane & 15;
    int dst = src ^ 1;

    const float4* __restrict__ xn4 = (const float4*)g_xn[src];
    const float*  __restrict__ sv  = g_s[src];
    int beg = g_rp[node], end = g_rp[node + 1];

    float4 x4 = xn4[node * 16 + lh];          // my 4 dims of xn[node]

    float4 acc = make_float4(0.f, 0.f, 0.f, 0.f);
    float ws = 0.f;

    for (int e0 = beg; e0 < end; e0 += 2) {
        int e = e0 + half;
        bool valid = (e < end);
        int c = __ldg(&colv[valid ? e : e0]);
        float4 y4 = xn4[c * 16 + lh];          // contiguous 256B per half
        float s = __ldg(&sv[c]);

        float p = x4.x * y4.x;
        p = fmaf(x4.y, y4.y, p);
        p = fmaf(x4.z, y4.z, p);
        p = fmaf(x4.w, y4.w, p);
        p += __shfl_xor_sync(0xffffffffu, p, 1);
        p += __shfl_xor_sync(0xffffffffu, p, 2);
        p += __shfl_xor_sync(0xffffffffu, p, 4);
        p += __shfl_xor_sync(0xffffffffu, p, 8);

        float ev = valid ? __expf(p) : 0.f;    // cosine: no max-shift needed
        ws += ev;
        float w = ev * s;                      // fold ||h_c|| back in
        acc.x = fmaf(w, y4.x, acc.x);
        acc.y = fmaf(w, y4.y, acc.y);
        acc.z = fmaf(w, y4.z, acc.z);
        acc.w = fmaf(w, y4.w, acc.w);
    }

    // merge the two half-warp accumulators
    ws    += __shfl_xor_sync(0xffffffffu, ws, 16);
    acc.x += __shfl_xor_sync(0xffffffffu, acc.x, 16);
    acc.y += __shfl_xor_sync(0xffffffffu, acc.y, 16);
    acc.z += __shfl_xor_sync(0xffffffffu, acc.z, 16);
    acc.w += __shfl_xor_sync(0xffffffffu, acc.w, 16);

    float inv = 1.0f / fmaxf(ws, 1e-12f);      // isolated node -> out = 0
    float4 o;
    o.x = fmaxf(acc.x * inv, 0.f);
    o.y = fmaxf(acc.y * inv, 0.f);
    o.z = fmaxf(acc.z * inv, 0.f);
    o.w = fmaxf(acc.w * inv, 0.f);

    if (LAST) {
        if (half == 0)
            ((float4*)g_h)[node * 16 + lh] = o;
    } else {
        // fused normalize for the next layer
        float pp = o.x * o.x;
        pp = fmaf(o.y, o.y, pp);
        pp = fmaf(o.z, o.z, pp);
        pp = fmaf(o.w, o.w, pp);
        pp += __shfl_xor_sync(0xffffffffu, pp, 1);
        pp += __shfl_xor_sync(0xffffffffu, pp, 2);
        pp += __shfl_xor_sync(0xffffffffu, pp, 4);
        pp += __shfl_xor_sync(0xffffffffu, pp, 8);
        float nrm = sqrtf(pp) + 1e-12f;
        float iv = 1.0f / nrm;
        if (half == 0) {
            ((float4*)g_xn[dst])[node * 16 + lh] =
                make_float4(o.x * iv, o.y * iv, o.z * iv, o.w * iv);
            if (lh == 0) g_s[dst][node] = nrm;
        }
    }
}

// ---------------------------------------------------------------------------
// GEMM2 (K=64): out = g_h @ W2^T + b2
// ---------------------------------------------------------------------------
__global__ void gemm2_kernel(const float* __restrict__ W,
                             const float* __restrict__ b,
                             float* __restrict__ out, int N) {
    __shared__ float Wt[HID * 64];
    for (int i = threadIdx.x; i < 64 * HID; i += blockDim.x) {
        int o = i / HID, k = i % HID;
        Wt[k * 64 + o] = W[i];
    }
    __syncthreads();

    int warp = threadIdx.x >> 5, lane = threadIdx.x & 31;
    int row0 = (blockIdx.x * 8 + warp) * 4;
    if (row0 >= N) return;

    float xf[4][2];
#pragma unroll
    for (int r = 0; r < 4; r++) {
        int row = min(row0 + r, N - 1);
        const float* xr = g_h + (size_t)row * HID;
#pragma unroll
        for (int j = 0; j < 2; j++) xf[r][j] = xr[j * 32 + lane];
    }

    float2 acc[4];
#pragma unroll
    for (int r = 0; r < 4; r++) acc[r] = make_float2(0.f, 0.f);

#pragma unroll
    for (int j = 0; j < 2; j++) {
#pragma unroll
        for (int kk = 0; kk < 32; kk++) {
            float2 w = *(const float2*)&Wt[(j * 32 + kk) * 64 + 2 * lane];
#pragma unroll
            for (int r = 0; r < 4; r++) {
                float bx = __shfl_sync(0xffffffffu, xf[r][j], kk);
                acc[r].x = fmaf(bx, w.x, acc[r].x);
                acc[r].y = fmaf(bx, w.y, acc[r].y);
            }
        }
    }

    float2 bias = ((const float2*)b)[lane];
#pragma unroll
    for (int r = 0; r < 4; r++) {
        int row = row0 + r;
        if (row < N) {
            ((float2*)out)[(size_t)row * 32 + lane] =
                make_float2(acc[r].x + bias.x, acc[r].y + bias.y);
        }
    }
}

// ---------------------------------------------------------------------------
extern "C" void kernel_launch(void* const* d_in, const int* in_sizes, int n_in,
                              void* d_out, int out_size) {
    const float* x    = (const float*)d_in[0];
    const int*   erow = (const int*)d_in[1];
    const int*   ecol = (const int*)d_in[2];
    const float* W1   = (const float*)d_in[3];
    const float* b1   = (const float*)d_in[4];
    const float* W2   = (const float*)d_in[5];
    const float* b2   = (const float*)d_in[6];

    int N = in_sizes[0] / IN_DIM;
    int E = in_sizes[1];

    rowptr_kernel<<<(N + 1 + 255) / 256, 256>>>(erow, N, E);

    int gemm_blocks = (N + 31) / 32;
    int node_blocks = (N + 7) / 8;

    gemm1_norm_kernel<<<gemm_blocks, 256>>>(x, W1, b1, N);

    prop_kernel<false><<<node_blocks, 256>>>(ecol, 0, N);
    prop_kernel<false><<<node_blocks, 256>>>(ecol, 1, N);
    prop_kernel<false><<<node_blocks, 256>>>(ecol, 0, N);
    prop_kernel<true ><<<node_blocks, 256>>>(ecol, 1, N);

    gemm2_kernel<<<gemm_blocks, 256>>>(W2, b2, (float*)d_out, N);
}

// round 5
// speedup vs baseline: 1.6340x; 1.0543x over previous
#include <cuda_runtime.h>
#include <cuda_bf16.h>
#include <math.h>

#define MAXN 100000
#define IN_DIM 128
#define HID 64

// Scratch (device globals — allocation-free rule)
__device__ float g_h[(size_t)MAXN * HID];        // last-layer output for GEMM2
__device__ float g_xn[2][(size_t)MAXN * HID];    // ping-pong unit-norm features
__device__ float g_s[2][MAXN];                   // ping-pong norms (+eps)
__device__ int   g_rp[MAXN + 1];                 // CSR row pointer

// ---------------------------------------------------------------------------
// row_ptr via binary search (edge_row sorted ascending)
// ---------------------------------------------------------------------------
__global__ void rowptr_kernel(const int* __restrict__ row, int N, int E) {
    int t = blockIdx.x * blockDim.x + threadIdx.x;
    if (t > N) return;
    int lo = 0, hi = E;
    while (lo < hi) {
        int mid = (lo + hi) >> 1;
        if (row[mid] < t) lo = mid + 1; else hi = mid;
    }
    g_rp[t] = lo;
}

// ---------------------------------------------------------------------------
// Skinny GEMM, no shfl broadcast: x fragments via warp-uniform LDG.128
// (1 sector/inst, L1-hot within each 128B line), W transposed in smem.
// Warp computes 4 rows; lane owns 2 output cols.
// NORM: fused relu + unit-normalize epilogue -> g_xn[0]/g_s[0].
// !NORM: reads g_h, writes out + bias.
// ---------------------------------------------------------------------------
template <int K, bool NORM>
__global__ void gemm_kernel(const float* __restrict__ x_ext,
                            const float* __restrict__ W,
                            const float* __restrict__ b,
                            float* __restrict__ out_ext, int N) {
    __shared__ float Wt[K * 64];
    for (int i = threadIdx.x; i < 64 * K; i += blockDim.x) {
        int o = i / K, k = i % K;
        Wt[k * 64 + o] = W[i];
    }
    __syncthreads();

    const float* xp = NORM ? x_ext : g_h;

    int warp = threadIdx.x >> 5, lane = threadIdx.x & 31;
    int row0 = (blockIdx.x * 8 + warp) * 4;
    if (row0 >= N) return;

    const float* xr0 = xp + (size_t)min(row0 + 0, N - 1) * K;
    const float* xr1 = xp + (size_t)min(row0 + 1, N - 1) * K;
    const float* xr2 = xp + (size_t)min(row0 + 2, N - 1) * K;
    const float* xr3 = xp + (size_t)min(row0 + 3, N - 1) * K;

    float2 acc[4];
#pragma unroll
    for (int r = 0; r < 4; r++) acc[r] = make_float2(0.f, 0.f);

#pragma unroll 4
    for (int k = 0; k < K; k += 4) {
        float4 xv0 = *(const float4*)(xr0 + k);
        float4 xv1 = *(const float4*)(xr1 + k);
        float4 xv2 = *(const float4*)(xr2 + k);
        float4 xv3 = *(const float4*)(xr3 + k);
        const float* f0 = (const float*)&xv0;
        const float* f1 = (const float*)&xv1;
        const float* f2 = (const float*)&xv2;
        const float* f3 = (const float*)&xv3;
#pragma unroll
        for (int kk = 0; kk < 4; kk++) {
            float2 w = *(const float2*)&Wt[(k + kk) * 64 + 2 * lane];
            acc[0].x = fmaf(f0[kk], w.x, acc[0].x);
            acc[0].y = fmaf(f0[kk], w.y, acc[0].y);
            acc[1].x = fmaf(f1[kk], w.x, acc[1].x);
            acc[1].y = fmaf(f1[kk], w.y, acc[1].y);
            acc[2].x = fmaf(f2[kk], w.x, acc[2].x);
            acc[2].y = fmaf(f2[kk], w.y, acc[2].y);
            acc[3].x = fmaf(f3[kk], w.x, acc[3].x);
            acc[3].y = fmaf(f3[kk], w.y, acc[3].y);
        }
    }

    float2 bias = ((const float2*)b)[lane];
#pragma unroll
    for (int r = 0; r < 4; r++) {
        int row = row0 + r;
        if (row >= N) break;
        if (NORM) {
            float fx = fmaxf(acc[r].x + bias.x, 0.f);
            float fy = fmaxf(acc[r].y + bias.y, 0.f);
            float p = fx * fx + fy * fy;
            p += __shfl_xor_sync(0xffffffffu, p, 16);
            p += __shfl_xor_sync(0xffffffffu, p, 8);
            p += __shfl_xor_sync(0xffffffffu, p, 4);
            p += __shfl_xor_sync(0xffffffffu, p, 2);
            p += __shfl_xor_sync(0xffffffffu, p, 1);
            float nrm = sqrtf(p) + 1e-12f;
            float inv = 1.0f / nrm;
            ((float2*)g_xn[0])[(size_t)row * 32 + lane] =
                make_float2(fx * inv, fy * inv);
            if (lane == 0) g_s[0][row] = nrm;
        } else {
            ((float2*)out_ext)[(size_t)row * 32 + lane] =
                make_float2(acc[r].x + bias.x, acc[r].y + bias.y);
        }
    }
}

// ---------------------------------------------------------------------------
// AGNN propagation + ReLU (+ fused normalize unless LAST).
// Warp per destination node; QUARTER-warp (8 lanes) per edge, 4 edges in
// flight. Lane lq loads xn4[c*16 + lq] and xn4[c*16 + 8 + lq]: each LDG.128
// warp-inst covers 4 full 128B lines (one per edge) — fully coalesced.
// Dot reduce = 3 shfls (within quarter). exp(p) shift-free: p = cos in [-1,1].
// ---------------------------------------------------------------------------
template <bool LAST>
__global__ void prop_kernel(const int* __restrict__ colv, int src, int N) {
    int node = blockIdx.x * 8 + (threadIdx.x >> 5);
    if (node >= N) return;
    int lane = threadIdx.x & 31;
    int q = lane >> 3, lq = lane & 7;
    int dst = src ^ 1;

    const float4* __restrict__ xn4 = (const float4*)g_xn[src];
    const float*  __restrict__ sv  = g_s[src];
    int beg = g_rp[node], end = g_rp[node + 1];

    float4 xa = xn4[node * 16 + lq];        // dims [4lq, 4lq+4)
    float4 xb = xn4[node * 16 + 8 + lq];    // dims [32+4lq, 32+4lq+4)

    float4 aa = make_float4(0.f, 0.f, 0.f, 0.f);
    float4 ab = make_float4(0.f, 0.f, 0.f, 0.f);
    float ws = 0.f;

    for (int e0 = beg; e0 < end; e0 += 4) {
        int e = e0 + q;
        bool valid = (e < end);
        int c = __ldg(&colv[valid ? e : beg]);
        float4 ya = xn4[c * 16 + lq];       // 4 full 128B lines per warp-inst
        float4 yb = xn4[c * 16 + 8 + lq];
        float s = __ldg(&sv[c]);

        float p = xa.x * ya.x;
        p = fmaf(xa.y, ya.y, p);
        p = fmaf(xa.z, ya.z, p);
        p = fmaf(xa.w, ya.w, p);
        p = fmaf(xb.x, yb.x, p);
        p = fmaf(xb.y, yb.y, p);
        p = fmaf(xb.z, yb.z, p);
        p = fmaf(xb.w, yb.w, p);
        p += __shfl_xor_sync(0xffffffffu, p, 1);
        p += __shfl_xor_sync(0xffffffffu, p, 2);
        p += __shfl_xor_sync(0xffffffffu, p, 4);

        float ev = valid ? __expf(p) : 0.f;  // cosine in [-1,1]: shift-free
        ws += ev;
        float w = ev * s;                    // fold ||h_c|| back in
        aa.x = fmaf(w, ya.x, aa.x);
        aa.y = fmaf(w, ya.y, aa.y);
        aa.z = fmaf(w, ya.z, aa.z);
        aa.w = fmaf(w, ya.w, aa.w);
        ab.x = fmaf(w, yb.x, ab.x);
        ab.y = fmaf(w, yb.y, ab.y);
        ab.z = fmaf(w, yb.z, ab.z);
        ab.w = fmaf(w, yb.w, ab.w);
    }

    // merge the 4 quarter-accumulators (butterfly across lanes 8, 16)
#pragma unroll
    for (int m = 8; m <= 16; m <<= 1) {
        ws   += __shfl_xor_sync(0xffffffffu, ws, m);
        aa.x += __shfl_xor_sync(0xffffffffu, aa.x, m);
        aa.y += __shfl_xor_sync(0xffffffffu, aa.y, m);
        aa.z += __shfl_xor_sync(0xffffffffu, aa.z, m);
        aa.w += __shfl_xor_sync(0xffffffffu, aa.w, m);
        ab.x += __shfl_xor_sync(0xffffffffu, ab.x, m);
        ab.y += __shfl_xor_sync(0xffffffffu, ab.y, m);
        ab.z += __shfl_xor_sync(0xffffffffu, ab.z, m);
        ab.w += __shfl_xor_sync(0xffffffffu, ab.w, m);
    }

    float inv = 1.0f / fmaxf(ws, 1e-12f);    // isolated node -> out = 0
    float4 oa, ob;
    oa.x = fmaxf(aa.x * inv, 0.f);
    oa.y = fmaxf(aa.y * inv, 0.f);
    oa.z = fmaxf(aa.z * inv, 0.f);
    oa.w = fmaxf(aa.w * inv, 0.f);
    ob.x = fmaxf(ab.x * inv, 0.f);
    ob.y = fmaxf(ab.y * inv, 0.f);
    ob.z = fmaxf(ab.z * inv, 0.f);
    ob.w = fmaxf(ab.w * inv, 0.f);

    if (LAST) {
        if (q == 0) {
            ((float4*)g_h)[node * 16 + lq]     = oa;
            ((float4*)g_h)[node * 16 + 8 + lq] = ob;
        }
    } else {
        // fused normalize for the next layer
        float pp = oa.x * oa.x;
        pp = fmaf(oa.y, oa.y, pp);
        pp = fmaf(oa.z, oa.z, pp);
        pp = fmaf(oa.w, oa.w, pp);
        pp = fmaf(ob.x, ob.x, pp);
        pp = fmaf(ob.y, ob.y, pp);
        pp = fmaf(ob.z, ob.z, pp);
        pp = fmaf(ob.w, ob.w, pp);
        pp += __shfl_xor_sync(0xffffffffu, pp, 1);
        pp += __shfl_xor_sync(0xffffffffu, pp, 2);
        pp += __shfl_xor_sync(0xffffffffu, pp, 4);
        float nrm = sqrtf(pp) + 1e-12f;
        float iv = 1.0f / nrm;
        if (q == 0) {
            ((float4*)g_xn[dst])[node * 16 + lq] =
                make_float4(oa.x * iv, oa.y * iv, oa.z * iv, oa.w * iv);
            ((float4*)g_xn[dst])[node * 16 + 8 + lq] =
                make_float4(ob.x * iv, ob.y * iv, ob.z * iv, ob.w * iv);
            if (lq == 0) g_s[dst][node] = nrm;
        }
    }
}

// ---------------------------------------------------------------------------
extern "C" void kernel_launch(void* const* d_in, const int* in_sizes, int n_in,
                              void* d_out, int out_size) {
    const float* x    = (const float*)d_in[0];
    const int*   erow = (const int*)d_in[1];
    const int*   ecol = (const int*)d_in[2];
    const float* W1   = (const float*)d_in[3];
    const float* b1   = (const float*)d_in[4];
    const float* W2   = (const float*)d_in[5];
    const float* b2   = (const float*)d_in[6];

    int N = in_sizes[0] / IN_DIM;
    int E = in_sizes[1];

    rowptr_kernel<<<(N + 1 + 255) / 256, 256>>>(erow, N, E);

    int gemm_blocks = (N + 31) / 32;
    int node_blocks = (N + 7) / 8;

    // h0 = relu(x @ W1^T + b1), fused normalize -> g_xn[0], g_s[0]
    gemm_kernel<IN_DIM, true><<<gemm_blocks, 256>>>(x, W1, b1, nullptr, N);

    prop_kernel<false><<<node_blocks, 256>>>(ecol, 0, N);
    prop_kernel<false><<<node_blocks, 256>>>(ecol, 1, N);
    prop_kernel<false><<<node_blocks, 256>>>(ecol, 0, N);
    prop_kernel<true ><<<node_blocks, 256>>>(ecol, 1, N);

    // out = g_h @ W2^T + b2
    gemm_kernel<HID, false><<<gemm_blocks, 256>>>(nullptr, W2, b2,
                                                  (float*)d_out, N);
}

// round 6
// speedup vs baseline: 1.9891x; 1.2173x over previous
#include <cuda_runtime.h>
#include <cuda_bf16.h>
#include <math.h>

#define MAXN 100000
#define IN_DIM 128
#define HID 64

// Scratch (device globals — allocation-free rule)
__device__ float g_h[(size_t)MAXN * HID];        // last-layer output for GEMM2
__device__ float g_xn[2][(size_t)MAXN * HID];    // ping-pong unit-norm features
__device__ float g_s[2][MAXN];                   // ping-pong norms (+eps)
__device__ int   g_rp[MAXN + 1];                 // CSR row pointer

// ---------------------------------------------------------------------------
// row_ptr via binary search (edge_row sorted ascending)
// ---------------------------------------------------------------------------
__global__ void rowptr_kernel(const int* __restrict__ row, int N, int E) {
    int t = blockIdx.x * blockDim.x + threadIdx.x;
    if (t > N) return;
    int lo = 0, hi = E;
    while (lo < hi) {
        int mid = (lo + hi) >> 1;
        if (row[mid] < t) lo = mid + 1; else hi = mid;
    }
    g_rp[t] = lo;
}

// ---------------------------------------------------------------------------
// Skinny GEMM: warp computes 8 rows, lane owns 2 output cols.
// W transposed in smem (1 LDS.64 feeds 16 FFMA). x via warp-uniform LDG.128.
// NORM: fused relu + unit-normalize epilogue -> g_xn[0]/g_s[0].
// !NORM: reads g_h, writes out + bias.
// ---------------------------------------------------------------------------
template <int K, bool NORM>
__global__ void __launch_bounds__(256)
gemm_kernel(const float* __restrict__ x_ext,
            const float* __restrict__ W,
            const float* __restrict__ b,
            float* __restrict__ out_ext, int N) {
    __shared__ float Wt[K * 64];
    for (int i = threadIdx.x; i < 64 * K; i += blockDim.x) {
        int o = i / K, k = i % K;
        Wt[k * 64 + o] = W[i];
    }
    __syncthreads();

    const float* xp = NORM ? x_ext : g_h;

    int warp = threadIdx.x >> 5, lane = threadIdx.x & 31;
    int row0 = (blockIdx.x * 8 + warp) * 8;
    if (row0 >= N) return;

    const float* xr[8];
#pragma unroll
    for (int r = 0; r < 8; r++)
        xr[r] = xp + (size_t)min(row0 + r, N - 1) * K;

    float2 acc[8];
#pragma unroll
    for (int r = 0; r < 8; r++) acc[r] = make_float2(0.f, 0.f);

#pragma unroll 2
    for (int k = 0; k < K; k += 4) {
        float4 xv[8];
#pragma unroll
        for (int r = 0; r < 8; r++)
            xv[r] = *(const float4*)(xr[r] + k);   // warp-uniform, 1 sector
#pragma unroll
        for (int kk = 0; kk < 4; kk++) {
            float2 w = *(const float2*)&Wt[(k + kk) * 64 + 2 * lane];
#pragma unroll
            for (int r = 0; r < 8; r++) {
                float xs = ((const float*)&xv[r])[kk];
                acc[r].x = fmaf(xs, w.x, acc[r].x);
                acc[r].y = fmaf(xs, w.y, acc[r].y);
            }
        }
    }

    float2 bias = ((const float2*)b)[lane];
#pragma unroll
    for (int r = 0; r < 8; r++) {
        int row = row0 + r;
        if (row >= N) break;
        if (NORM) {
            float fx = fmaxf(acc[r].x + bias.x, 0.f);
            float fy = fmaxf(acc[r].y + bias.y, 0.f);
            float p = fx * fx + fy * fy;
            p += __shfl_xor_sync(0xffffffffu, p, 16);
            p += __shfl_xor_sync(0xffffffffu, p, 8);
            p += __shfl_xor_sync(0xffffffffu, p, 4);
            p += __shfl_xor_sync(0xffffffffu, p, 2);
            p += __shfl_xor_sync(0xffffffffu, p, 1);
            float nrm = sqrtf(p) + 1e-12f;
            float inv = 1.0f / nrm;
            ((float2*)g_xn[0])[(size_t)row * 32 + lane] =
                make_float2(fx * inv, fy * inv);
            if (lane == 0) g_s[0][row] = nrm;
        } else {
            ((float2*)out_ext)[(size_t)row * 32 + lane] =
                make_float2(acc[r].x + bias.x, acc[r].y + bias.y);
        }
    }
}

// ---------------------------------------------------------------------------
// AGNN propagation + ReLU (+ fused normalize unless LAST).
// Warp per destination node; QUARTER-warp (8 lanes) per edge; TWO independent
// edge-chains per iteration (8 edges in flight) so the shfl/exp latency of
// chain A overlaps with chain B.  Loads fully coalesced (each LDG.128
// warp-inst covers 4 distinct 128B lines).  exp(p) shift-free: p=cos in [-1,1].
// ---------------------------------------------------------------------------
template <bool LAST>
__global__ void __launch_bounds__(256, 4)
prop_kernel(const int* __restrict__ colv, int src, int N) {
    int node = blockIdx.x * 8 + (threadIdx.x >> 5);
    if (node >= N) return;
    int lane = threadIdx.x & 31;
    int q = lane >> 3, lq = lane & 7;
    int dst = src ^ 1;

    const float4* __restrict__ xn4 = (const float4*)g_xn[src];
    const float*  __restrict__ sv  = g_s[src];
    int beg = g_rp[node], end = g_rp[node + 1];

    float4 xa = xn4[node * 16 + lq];        // dims [4lq, 4lq+4)
    float4 xb = xn4[node * 16 + 8 + lq];    // dims [32+4lq, ...)

    float4 aa = make_float4(0.f, 0.f, 0.f, 0.f);
    float4 ab = make_float4(0.f, 0.f, 0.f, 0.f);
    float ws = 0.f;

    for (int e0 = beg; e0 < end; e0 += 8) {
        int eA = e0 + q, eB = e0 + 4 + q;
        bool vA = (eA < end), vB = (eB < end);
        int cA = __ldg(&colv[vA ? eA : beg]);
        int cB = __ldg(&colv[vB ? eB : beg]);
        // all 6 vector loads issue up front -> 6-deep MLP per warp
        float4 yaA = xn4[cA * 16 + lq];
        float4 ybA = xn4[cA * 16 + 8 + lq];
        float4 yaB = xn4[cB * 16 + lq];
        float4 ybB = xn4[cB * 16 + 8 + lq];
        float sA = __ldg(&sv[cA]);
        float sB = __ldg(&sv[cB]);

        float pA = xa.x * yaA.x;
        float pB = xa.x * yaB.x;
        pA = fmaf(xa.y, yaA.y, pA);  pB = fmaf(xa.y, yaB.y, pB);
        pA = fmaf(xa.z, yaA.z, pA);  pB = fmaf(xa.z, yaB.z, pB);
        pA = fmaf(xa.w, yaA.w, pA);  pB = fmaf(xa.w, yaB.w, pB);
        pA = fmaf(xb.x, ybA.x, pA);  pB = fmaf(xb.x, ybB.x, pB);
        pA = fmaf(xb.y, ybA.y, pA);  pB = fmaf(xb.y, ybB.y, pB);
        pA = fmaf(xb.z, ybA.z, pA);  pB = fmaf(xb.z, ybB.z, pB);
        pA = fmaf(xb.w, ybA.w, pA);  pB = fmaf(xb.w, ybB.w, pB);

        pA += __shfl_xor_sync(0xffffffffu, pA, 1);
        pB += __shfl_xor_sync(0xffffffffu, pB, 1);
        pA += __shfl_xor_sync(0xffffffffu, pA, 2);
        pB += __shfl_xor_sync(0xffffffffu, pB, 2);
        pA += __shfl_xor_sync(0xffffffffu, pA, 4);
        pB += __shfl_xor_sync(0xffffffffu, pB, 4);

        float evA = vA ? __expf(pA) : 0.f;   // cosine in [-1,1]: shift-free
        float evB = vB ? __expf(pB) : 0.f;
        ws += evA + evB;
        float wA = evA * sA, wB = evB * sB;  // fold ||h_c|| back in

        aa.x = fmaf(wA, yaA.x, aa.x);  aa.x = fmaf(wB, yaB.x, aa.x);
        aa.y = fmaf(wA, yaA.y, aa.y);  aa.y = fmaf(wB, yaB.y, aa.y);
        aa.z = fmaf(wA, yaA.z, aa.z);  aa.z = fmaf(wB, yaB.z, aa.z);
        aa.w = fmaf(wA, yaA.w, aa.w);  aa.w = fmaf(wB, yaB.w, aa.w);
        ab.x = fmaf(wA, ybA.x, ab.x);  ab.x = fmaf(wB, ybB.x, ab.x);
        ab.y = fmaf(wA, ybA.y, ab.y);  ab.y = fmaf(wB, ybB.y, ab.y);
        ab.z = fmaf(wA, ybA.z, ab.z);  ab.z = fmaf(wB, ybB.z, ab.z);
        ab.w = fmaf(wA, ybA.w, ab.w);  ab.w = fmaf(wB, ybB.w, ab.w);
    }

    // merge the 4 quarter-accumulators (butterfly across lanes 8, 16)
#pragma unroll
    for (int m = 8; m <= 16; m <<= 1) {
        ws   += __shfl_xor_sync(0xffffffffu, ws, m);
        aa.x += __shfl_xor_sync(0xffffffffu, aa.x, m);
        aa.y += __shfl_xor_sync(0xffffffffu, aa.y, m);
        aa.z += __shfl_xor_sync(0xffffffffu, aa.z, m);
        aa.w += __shfl_xor_sync(0xffffffffu, aa.w, m);
        ab.x += __shfl_xor_sync(0xffffffffu, ab.x, m);
        ab.y += __shfl_xor_sync(0xffffffffu, ab.y, m);
        ab.z += __shfl_xor_sync(0xffffffffu, ab.z, m);
        ab.w += __shfl_xor_sync(0xffffffffu, ab.w, m);
    }

    float inv = 1.0f / fmaxf(ws, 1e-12f);    // isolated node -> out = 0
    float4 oa, ob;
    oa.x = fmaxf(aa.x * inv, 0.f);
    oa.y = fmaxf(aa.y * inv, 0.f);
    oa.z = fmaxf(aa.z * inv, 0.f);
    oa.w = fmaxf(aa.w * inv, 0.f);
    ob.x = fmaxf(ab.x * inv, 0.f);
    ob.y = fmaxf(ab.y * inv, 0.f);
    ob.z = fmaxf(ab.z * inv, 0.f);
    ob.w = fmaxf(ab.w * inv, 0.f);

    if (LAST) {
        if (q == 0) {
            ((float4*)g_h)[node * 16 + lq]     = oa;
            ((float4*)g_h)[node * 16 + 8 + lq] = ob;
        }
    } else {
        // fused normalize for the next layer
        float pp = oa.x * oa.x;
        pp = fmaf(oa.y, oa.y, pp);
        pp = fmaf(oa.z, oa.z, pp);
        pp = fmaf(oa.w, oa.w, pp);
        pp = fmaf(ob.x, ob.x, pp);
        pp = fmaf(ob.y, ob.y, pp);
        pp = fmaf(ob.z, ob.z, pp);
        pp = fmaf(ob.w, ob.w, pp);
        pp += __shfl_xor_sync(0xffffffffu, pp, 1);
        pp += __shfl_xor_sync(0xffffffffu, pp, 2);
        pp += __shfl_xor_sync(0xffffffffu, pp, 4);
        float nrm = sqrtf(pp) + 1e-12f;
        float iv = 1.0f / nrm;
        if (q == 0) {
            ((float4*)g_xn[dst])[node * 16 + lq] =
                make_float4(oa.x * iv, oa.y * iv, oa.z * iv, oa.w * iv);
            ((float4*)g_xn[dst])[node * 16 + 8 + lq] =
                make_float4(ob.x * iv, ob.y * iv, ob.z * iv, ob.w * iv);
            if (lq == 0) g_s[dst][node] = nrm;
        }
    }
}

// ---------------------------------------------------------------------------
extern "C" void kernel_launch(void* const* d_in, const int* in_sizes, int n_in,
                              void* d_out, int out_size) {
    const float* x    = (const float*)d_in[0];
    const int*   erow = (const int*)d_in[1];
    const int*   ecol = (const int*)d_in[2];
    const float* W1   = (const float*)d_in[3];
    const float* b1   = (const float*)d_in[4];
    const float* W2   = (const float*)d_in[5];
    const float* b2   = (const float*)d_in[6];

    int N = in_sizes[0] / IN_DIM;
    int E = in_sizes[1];

    rowptr_kernel<<<(N + 1 + 255) / 256, 256>>>(erow, N, E);

    int gemm_blocks = (N + 63) / 64;    // 8 warps * 8 rows
    int node_blocks = (N + 7) / 8;

    // h0 = relu(x @ W1^T + b1), fused normalize -> g_xn[0], g_s[0]
    gemm_kernel<IN_DIM, true><<<gemm_blocks, 256>>>(x, W1, b1, nullptr, N);

    prop_kernel<false><<<node_blocks, 256>>>(ecol, 0, N);
    prop_kernel<false><<<node_blocks, 256>>>(ecol, 1, N);
    prop_kernel<false><<<node_blocks, 256>>>(ecol, 0, N);
    prop_kernel<true ><<<node_blocks, 256>>>(ecol, 1, N);

    // out = g_h @ W2^T + b2
    gemm_kernel<HID, false><<<gemm_blocks, 256>>>(nullptr, W2, b2,
                                                  (float*)d_out, N);
}

// round 7
// speedup vs baseline: 2.0189x; 1.0150x over previous
#include <cuda_runtime.h>
#include <cuda_bf16.h>
#include <math.h>

#define MAXN 100000
#define IN_DIM 128
#define HID 64

// Scratch (device globals — allocation-free rule)
__device__ float g_h[(size_t)MAXN * HID];        // last-layer output for GEMM2
__device__ float g_xn[2][(size_t)MAXN * HID];    // ping-pong unit-norm features
__device__ float g_s[2][MAXN];                   // ping-pong norms (+eps)
__device__ int   g_rp[MAXN + 1];                 // CSR row pointer

// ---------------------------------------------------------------------------
// row_ptr via binary search (edge_row sorted ascending)
// ---------------------------------------------------------------------------
__global__ void rowptr_kernel(const int* __restrict__ row, int N, int E) {
    int t = blockIdx.x * blockDim.x + threadIdx.x;
    if (t > N) return;
    int lo = 0, hi = E;
    while (lo < hi) {
        int mid = (lo + hi) >> 1;
        if (row[mid] < t) lo = mid + 1; else hi = mid;
    }
    g_rp[t] = lo;
}

// ---------------------------------------------------------------------------
// Skinny GEMM: warp computes 8 rows, lane owns 2 output cols.
// W transposed in smem (1 LDS.64 feeds 16 FFMA). x via warp-uniform LDG.128.
// NORM: fused relu + unit-normalize epilogue -> g_xn[0]/g_s[0].
// !NORM: reads g_h, writes out + bias.
// ---------------------------------------------------------------------------
template <int K, bool NORM>
__global__ void __launch_bounds__(256)
gemm_kernel(const float* __restrict__ x_ext,
            const float* __restrict__ W,
            const float* __restrict__ b,
            float* __restrict__ out_ext, int N) {
    __shared__ float Wt[K * 64];
    for (int i = threadIdx.x; i < 64 * K; i += blockDim.x) {
        int o = i / K, k = i % K;
        Wt[k * 64 + o] = W[i];
    }
    __syncthreads();

    const float* xp = NORM ? x_ext : g_h;

    int warp = threadIdx.x >> 5, lane = threadIdx.x & 31;
    int row0 = (blockIdx.x * 8 + warp) * 8;
    if (row0 >= N) return;

    const float* xr[8];
#pragma unroll
    for (int r = 0; r < 8; r++)
        xr[r] = xp + (size_t)min(row0 + r, N - 1) * K;

    float2 acc[8];
#pragma unroll
    for (int r = 0; r < 8; r++) acc[r] = make_float2(0.f, 0.f);

#pragma unroll 2
    for (int k = 0; k < K; k += 4) {
        float4 xv[8];
#pragma unroll
        for (int r = 0; r < 8; r++)
            xv[r] = *(const float4*)(xr[r] + k);   // warp-uniform, 1 sector
#pragma unroll
        for (int kk = 0; kk < 4; kk++) {
            float2 w = *(const float2*)&Wt[(k + kk) * 64 + 2 * lane];
#pragma unroll
            for (int r = 0; r < 8; r++) {
                float xs = ((const float*)&xv[r])[kk];
                acc[r].x = fmaf(xs, w.x, acc[r].x);
                acc[r].y = fmaf(xs, w.y, acc[r].y);
            }
        }
    }

    float2 bias = ((const float2*)b)[lane];
#pragma unroll
    for (int r = 0; r < 8; r++) {
        int row = row0 + r;
        if (row >= N) break;
        if (NORM) {
            float fx = fmaxf(acc[r].x + bias.x, 0.f);
            float fy = fmaxf(acc[r].y + bias.y, 0.f);
            float p = fx * fx + fy * fy;
            p += __shfl_xor_sync(0xffffffffu, p, 16);
            p += __shfl_xor_sync(0xffffffffu, p, 8);
            p += __shfl_xor_sync(0xffffffffu, p, 4);
            p += __shfl_xor_sync(0xffffffffu, p, 2);
            p += __shfl_xor_sync(0xffffffffu, p, 1);
            float nrm = sqrtf(p) + 1e-12f;
            float inv = 1.0f / nrm;
            ((float2*)g_xn[0])[(size_t)row * 32 + lane] =
                make_float2(fx * inv, fy * inv);
            if (lane == 0) g_s[0][row] = nrm;
        } else {
            ((float2*)out_ext)[(size_t)row * 32 + lane] =
                make_float2(acc[r].x + bias.x, acc[r].y + bias.y);
        }
    }
}

// ---------------------------------------------------------------------------
// AGNN propagation + ReLU (+ fused normalize unless LAST).
// Warp per destination node; QUARTER-warp (8 lanes) per edge; TWO independent
// edge-chains per iteration (8 edges in flight).  Column indices and s-values
// for iteration i+1 are PREFETCHED during iteration i, so y-loads issue with
// zero address latency at each loop head.  Loads fully coalesced (each
// LDG.128 warp-inst covers 4 distinct 128B lines).  exp(p) shift-free:
// p = cosine in [-1,1].
// ---------------------------------------------------------------------------
template <bool LAST>
__global__ void __launch_bounds__(256, 4)
prop_kernel(const int* __restrict__ colv, int src, int N) {
    int node = blockIdx.x * 8 + (threadIdx.x >> 5);
    if (node >= N) return;
    int lane = threadIdx.x & 31;
    int q = lane >> 3, lq = lane & 7;
    int dst = src ^ 1;

    const float4* __restrict__ xn4 = (const float4*)g_xn[src];
    const float*  __restrict__ sv  = g_s[src];
    int beg = g_rp[node], end = g_rp[node + 1];

    if (beg == end) {  // isolated node: out = 0 everywhere
        if (q == 0) {
            float4 z = make_float4(0.f, 0.f, 0.f, 0.f);
            if (LAST) {
                ((float4*)g_h)[node * 16 + lq]     = z;
                ((float4*)g_h)[node * 16 + 8 + lq] = z;
            } else {
                ((float4*)g_xn[dst])[node * 16 + lq]     = z;
                ((float4*)g_xn[dst])[node * 16 + 8 + lq] = z;
                if (lq == 0) g_s[dst][node] = 1e-12f;
            }
        }
        return;
    }

    float4 xa = xn4[node * 16 + lq];        // dims [4lq, 4lq+4)
    float4 xb = xn4[node * 16 + 8 + lq];    // dims [32+4lq, ...)

    float4 aa = make_float4(0.f, 0.f, 0.f, 0.f);
    float4 ab = make_float4(0.f, 0.f, 0.f, 0.f);
    float ws = 0.f;

    int last = end - 1;

    // prologue: resolve indices + s for the first iteration
    int   cA = __ldg(&colv[min(beg + q,     last)]);
    int   cB = __ldg(&colv[min(beg + 4 + q, last)]);
    float sA = __ldg(&sv[cA]);
    float sB = __ldg(&sv[cB]);

    for (int e0 = beg; e0 < end; e0 += 8) {
        // y-loads: addresses ready immediately (c prefetched last iteration)
        float4 yaA = xn4[cA * 16 + lq];
        float4 ybA = xn4[cA * 16 + 8 + lq];
        float4 yaB = xn4[cB * 16 + lq];
        float4 ybB = xn4[cB * 16 + 8 + lq];

        // prefetch next iteration's indices + s (off the critical path)
        int n0 = e0 + 8;
        int ncA = __ldg(&colv[min(n0 + q,     last)]);
        int ncB = __ldg(&colv[min(n0 + 4 + q, last)]);
        float nsA = __ldg(&sv[ncA]);
        float nsB = __ldg(&sv[ncB]);

        bool vA = (e0 + q     < end);
        bool vB = (e0 + 4 + q < end);

        float pA = xa.x * yaA.x;
        float pB = xa.x * yaB.x;
        pA = fmaf(xa.y, yaA.y, pA);  pB = fmaf(xa.y, yaB.y, pB);
        pA = fmaf(xa.z, yaA.z, pA);  pB = fmaf(xa.z, yaB.z, pB);
        pA = fmaf(xa.w, yaA.w, pA);  pB = fmaf(xa.w, yaB.w, pB);
        pA = fmaf(xb.x, ybA.x, pA);  pB = fmaf(xb.x, ybB.x, pB);
        pA = fmaf(xb.y, ybA.y, pA);  pB = fmaf(xb.y, ybB.y, pB);
        pA = fmaf(xb.z, ybA.z, pA);  pB = fmaf(xb.z, ybB.z, pB);
        pA = fmaf(xb.w, ybA.w, pA);  pB = fmaf(xb.w, ybB.w, pB);

        pA += __shfl_xor_sync(0xffffffffu, pA, 1);
        pB += __shfl_xor_sync(0xffffffffu, pB, 1);
        pA += __shfl_xor_sync(0xffffffffu, pA, 2);
        pB += __shfl_xor_sync(0xffffffffu, pB, 2);
        pA += __shfl_xor_sync(0xffffffffu, pA, 4);
        pB += __shfl_xor_sync(0xffffffffu, pB, 4);

        float evA = vA ? __expf(pA) : 0.f;   // cosine in [-1,1]: shift-free
        float evB = vB ? __expf(pB) : 0.f;
        ws += evA + evB;
        float wA = evA * sA, wB = evB * sB;  // fold ||h_c|| back in

        aa.x = fmaf(wA, yaA.x, aa.x);  aa.x = fmaf(wB, yaB.x, aa.x);
        aa.y = fmaf(wA, yaA.y, aa.y);  aa.y = fmaf(wB, yaB.y, aa.y);
        aa.z = fmaf(wA, yaA.z, aa.z);  aa.z = fmaf(wB, yaB.z, aa.z);
        aa.w = fmaf(wA, yaA.w, aa.w);  aa.w = fmaf(wB, yaB.w, aa.w);
        ab.x = fmaf(wA, ybA.x, ab.x);  ab.x = fmaf(wB, ybB.x, ab.x);
        ab.y = fmaf(wA, ybA.y, ab.y);  ab.y = fmaf(wB, ybB.y, ab.y);
        ab.z = fmaf(wA, ybA.z, ab.z);  ab.z = fmaf(wB, ybB.z, ab.z);
        ab.w = fmaf(wA, ybA.w, ab.w);  ab.w = fmaf(wB, ybB.w, ab.w);

        cA = ncA; cB = ncB; sA = nsA; sB = nsB;
    }

    // merge the 4 quarter-accumulators (butterfly across lanes 8, 16)
#pragma unroll
    for (int m = 8; m <= 16; m <<= 1) {
        ws   += __shfl_xor_sync(0xffffffffu, ws, m);
        aa.x += __shfl_xor_sync(0xffffffffu, aa.x, m);
        aa.y += __shfl_xor_sync(0xffffffffu, aa.y, m);
        aa.z += __shfl_xor_sync(0xffffffffu, aa.z, m);
        aa.w += __shfl_xor_sync(0xffffffffu, aa.w, m);
        ab.x += __shfl_xor_sync(0xffffffffu, ab.x, m);
        ab.y += __shfl_xor_sync(0xffffffffu, ab.y, m);
        ab.z += __shfl_xor_sync(0xffffffffu, ab.z, m);
        ab.w += __shfl_xor_sync(0xffffffffu, ab.w, m);
    }

    float inv = 1.0f / fmaxf(ws, 1e-12f);
    float4 oa, ob;
    oa.x = fmaxf(aa.x * inv, 0.f);
    oa.y = fmaxf(aa.y * inv, 0.f);
    oa.z = fmaxf(aa.z * inv, 0.f);
    oa.w = fmaxf(aa.w * inv, 0.f);
    ob.x = fmaxf(ab.x * inv, 0.f);
    ob.y = fmaxf(ab.y * inv, 0.f);
    ob.z = fmaxf(ab.z * inv, 0.f);
    ob.w = fmaxf(ab.w * inv, 0.f);

    if (LAST) {
        if (q == 0) {
            ((float4*)g_h)[node * 16 + lq]     = oa;
            ((float4*)g_h)[node * 16 + 8 + lq] = ob;
        }
    } else {
        // fused normalize for the next layer
        float pp = oa.x * oa.x;
        pp = fmaf(oa.y, oa.y, pp);
        pp = fmaf(oa.z, oa.z, pp);
        pp = fmaf(oa.w, oa.w, pp);
        pp = fmaf(ob.x, ob.x, pp);
        pp = fmaf(ob.y, ob.y, pp);
        pp = fmaf(ob.z, ob.z, pp);
        pp = fmaf(ob.w, ob.w, pp);
        pp += __shfl_xor_sync(0xffffffffu, pp, 1);
        pp += __shfl_xor_sync(0xffffffffu, pp, 2);
        pp += __shfl_xor_sync(0xffffffffu, pp, 4);
        float nrm = sqrtf(pp) + 1e-12f;
        float iv = 1.0f / nrm;
        if (q == 0) {
            ((float4*)g_xn[dst])[node * 16 + lq] =
                make_float4(oa.x * iv, oa.y * iv, oa.z * iv, oa.w * iv);
            ((float4*)g_xn[dst])[node * 16 + 8 + lq] =
                make_float4(ob.x * iv, ob.y * iv, ob.z * iv, ob.w * iv);
            if (lq == 0) g_s[dst][node] = nrm;
        }
    }
}

// ---------------------------------------------------------------------------
extern "C" void kernel_launch(void* const* d_in, const int* in_sizes, int n_in,
                              void* d_out, int out_size) {
    const float* x    = (const float*)d_in[0];
    const int*   erow = (const int*)d_in[1];
    const int*   ecol = (const int*)d_in[2];
    const float* W1   = (const float*)d_in[3];
    const float* b1   = (const float*)d_in[4];
    const float* W2   = (const float*)d_in[5];
    const float* b2   = (const float*)d_in[6];

    int N = in_sizes[0] / IN_DIM;
    int E = in_sizes[1];

    rowptr_kernel<<<(N + 1 + 255) / 256, 256>>>(erow, N, E);

    int gemm_blocks = (N + 63) / 64;    // 8 warps * 8 rows
    int node_blocks = (N + 7) / 8;

    // h0 = relu(x @ W1^T + b1), fused normalize -> g_xn[0], g_s[0]
    gemm_kernel<IN_DIM, true><<<gemm_blocks, 256>>>(x, W1, b1, nullptr, N);

    prop_kernel<false><<<node_blocks, 256>>>(ecol, 0, N);
    prop_kernel<false><<<node_blocks, 256>>>(ecol, 1, N);
    prop_kernel<false><<<node_blocks, 256>>>(ecol, 0, N);
    prop_kernel<true ><<<node_blocks, 256>>>(ecol, 1, N);

    // out = g_h @ W2^T + b2
    gemm_kernel<HID, false><<<gemm_blocks, 256>>>(nullptr, W2, b2,
                                                  (float*)d_out, N);
}

// round 8
// speedup vs baseline: 2.1627x; 1.0712x over previous
#include <cuda_runtime.h>
#include <cuda_bf16.h>
#include <math.h>

#define MAXN 100000
#define IN_DIM 128
#define HID 64

#define PROP_BLOCKS 592          // 148 SMs * 4 CTAs resident (64 regs, 256 thr)
#define PROP_WARPS  (PROP_BLOCKS * 8)

// Scratch (device globals — allocation-free rule)
__device__ float g_h[(size_t)MAXN * HID];        // last-layer output for GEMM2
__device__ float g_xn[2][(size_t)MAXN * HID];    // ping-pong unit-norm features
__device__ float g_s[2][MAXN];                   // ping-pong norms (+eps)
__device__ int   g_rp[MAXN + 1];                 // CSR row pointer

// ---------------------------------------------------------------------------
// row_ptr via binary search (edge_row sorted ascending)
// ---------------------------------------------------------------------------
__global__ void rowptr_kernel(const int* __restrict__ row, int N, int E) {
    int t = blockIdx.x * blockDim.x + threadIdx.x;
    if (t > N) return;
    int lo = 0, hi = E;
    while (lo < hi) {
        int mid = (lo + hi) >> 1;
        if (row[mid] < t) lo = mid + 1; else hi = mid;
    }
    g_rp[t] = lo;
}

// ---------------------------------------------------------------------------
// Skinny GEMM: warp computes 8 rows per tile, grid-stride over row tiles.
// W transposed in smem (1 LDS.64 feeds 16 FFMA). x via warp-uniform LDG.128.
// NORM: fused relu + unit-normalize epilogue -> g_xn[0]/g_s[0].
// !NORM: reads g_h, writes out + bias.
// ---------------------------------------------------------------------------
template <int K, bool NORM>
__global__ void __launch_bounds__(256)
gemm_kernel(const float* __restrict__ x_ext,
            const float* __restrict__ W,
            const float* __restrict__ b,
            float* __restrict__ out_ext, int N) {
    __shared__ float Wt[K * 64];
    for (int i = threadIdx.x; i < 64 * K; i += blockDim.x) {
        int o = i / K, k = i % K;
        Wt[k * 64 + o] = W[i];
    }
    __syncthreads();

    const float* xp = NORM ? x_ext : g_h;

    int warp = threadIdx.x >> 5, lane = threadIdx.x & 31;
    int gwarp = blockIdx.x * 8 + warp;
    int nwarps = gridDim.x * 8;
    int ntiles = (N + 7) / 8;
    float2 bias = ((const float2*)b)[lane];

    for (int tile = gwarp; tile < ntiles; tile += nwarps) {
        int row0 = tile * 8;

        const float* xr[8];
#pragma unroll
        for (int r = 0; r < 8; r++)
            xr[r] = xp + (size_t)min(row0 + r, N - 1) * K;

        float2 acc[8];
#pragma unroll
        for (int r = 0; r < 8; r++) acc[r] = make_float2(0.f, 0.f);

#pragma unroll 2
        for (int k = 0; k < K; k += 4) {
            float4 xv[8];
#pragma unroll
            for (int r = 0; r < 8; r++)
                xv[r] = *(const float4*)(xr[r] + k);   // warp-uniform, 1 sector
#pragma unroll
            for (int kk = 0; kk < 4; kk++) {
                float2 w = *(const float2*)&Wt[(k + kk) * 64 + 2 * lane];
#pragma unroll
                for (int r = 0; r < 8; r++) {
                    float xs = ((const float*)&xv[r])[kk];
                    acc[r].x = fmaf(xs, w.x, acc[r].x);
                    acc[r].y = fmaf(xs, w.y, acc[r].y);
                }
            }
        }

#pragma unroll
        for (int r = 0; r < 8; r++) {
            int row = row0 + r;
            if (row >= N) break;
            if (NORM) {
                float fx = fmaxf(acc[r].x + bias.x, 0.f);
                float fy = fmaxf(acc[r].y + bias.y, 0.f);
                float p = fx * fx + fy * fy;
                p += __shfl_xor_sync(0xffffffffu, p, 16);
                p += __shfl_xor_sync(0xffffffffu, p, 8);
                p += __shfl_xor_sync(0xffffffffu, p, 4);
                p += __shfl_xor_sync(0xffffffffu, p, 2);
                p += __shfl_xor_sync(0xffffffffu, p, 1);
                float nrm = sqrtf(p) + 1e-12f;
                float inv = 1.0f / nrm;
                ((float2*)g_xn[0])[(size_t)row * 32 + lane] =
                    make_float2(fx * inv, fy * inv);
                if (lane == 0) g_s[0][row] = nrm;
            } else {
                ((float2*)out_ext)[(size_t)row * 32 + lane] =
                    make_float2(acc[r].x + bias.x, acc[r].y + bias.y);
            }
        }
    }
}

// ---------------------------------------------------------------------------
// AGNN propagation + ReLU (+ fused normalize unless LAST).
// PERSISTENT WARPS: exactly one wave of CTAs; each warp grid-strides over
// ~21 nodes so degree imbalance amortizes and warp slots never go dead.
// Per node: quarter-warp (8 lanes) per edge, TWO independent chains
// (8 edges in flight), col/s prefetch.  Loads fully coalesced.
// exp(p) shift-free: p = cosine in [-1,1].
// ---------------------------------------------------------------------------
template <bool LAST>
__global__ void __launch_bounds__(256, 4)
prop_kernel(const int* __restrict__ colv, int src, int N) {
    int lane = threadIdx.x & 31;
    int q = lane >> 3, lq = lane & 7;
    int dst = src ^ 1;
    int gwarp = blockIdx.x * 8 + (threadIdx.x >> 5);

    const float4* __restrict__ xn4 = (const float4*)g_xn[src];
    const float*  __restrict__ sv  = g_s[src];

    for (int node = gwarp; node < N; node += PROP_WARPS) {
        int beg = g_rp[node], end = g_rp[node + 1];

        if (beg == end) {  // isolated node: out = 0 everywhere
            if (q == 0) {
                float4 z = make_float4(0.f, 0.f, 0.f, 0.f);
                if (LAST) {
                    ((float4*)g_h)[node * 16 + lq]     = z;
                    ((float4*)g_h)[node * 16 + 8 + lq] = z;
                } else {
                    ((float4*)g_xn[dst])[node * 16 + lq]     = z;
                    ((float4*)g_xn[dst])[node * 16 + 8 + lq] = z;
                    if (lq == 0) g_s[dst][node] = 1e-12f;
                }
            }
            continue;
        }

        float4 xa = xn4[node * 16 + lq];        // dims [4lq, 4lq+4)
        float4 xb = xn4[node * 16 + 8 + lq];    // dims [32+4lq, ...)

        float4 aa = make_float4(0.f, 0.f, 0.f, 0.f);
        float4 ab = make_float4(0.f, 0.f, 0.f, 0.f);
        float ws = 0.f;

        int last = end - 1;

        // prologue: resolve indices + s for the first iteration
        int   cA = __ldg(&colv[min(beg + q,     last)]);
        int   cB = __ldg(&colv[min(beg + 4 + q, last)]);
        float sA = __ldg(&sv[cA]);
        float sB = __ldg(&sv[cB]);

        for (int e0 = beg; e0 < end; e0 += 8) {
            float4 yaA = xn4[cA * 16 + lq];
            float4 ybA = xn4[cA * 16 + 8 + lq];
            float4 yaB = xn4[cB * 16 + lq];
            float4 ybB = xn4[cB * 16 + 8 + lq];

            // prefetch next iteration's indices + s (off the critical path)
            int n0 = e0 + 8;
            int ncA = __ldg(&colv[min(n0 + q,     last)]);
            int ncB = __ldg(&colv[min(n0 + 4 + q, last)]);
            float nsA = __ldg(&sv[ncA]);
            float nsB = __ldg(&sv[ncB]);

            bool vA = (e0 + q     < end);
            bool vB = (e0 + 4 + q < end);

            float pA = xa.x * yaA.x;
            float pB = xa.x * yaB.x;
            pA = fmaf(xa.y, yaA.y, pA);  pB = fmaf(xa.y, yaB.y, pB);
            pA = fmaf(xa.z, yaA.z, pA);  pB = fmaf(xa.z, yaB.z, pB);
            pA = fmaf(xa.w, yaA.w, pA);  pB = fmaf(xa.w, yaB.w, pB);
            pA = fmaf(xb.x, ybA.x, pA);  pB = fmaf(xb.x, ybB.x, pB);
            pA = fmaf(xb.y, ybA.y, pA);  pB = fmaf(xb.y, ybB.y, pB);
            pA = fmaf(xb.z, ybA.z, pA);  pB = fmaf(xb.z, ybB.z, pB);
            pA = fmaf(xb.w, ybA.w, pA);  pB = fmaf(xb.w, ybB.w, pB);

            pA += __shfl_xor_sync(0xffffffffu, pA, 1);
            pB += __shfl_xor_sync(0xffffffffu, pB, 1);
            pA += __shfl_xor_sync(0xffffffffu, pA, 2);
            pB += __shfl_xor_sync(0xffffffffu, pB, 2);
            pA += __shfl_xor_sync(0xffffffffu, pA, 4);
            pB += __shfl_xor_sync(0xffffffffu, pB, 4);

            float evA = vA ? __expf(pA) : 0.f;   // cosine: shift-free exact
            float evB = vB ? __expf(pB) : 0.f;
            ws += evA + evB;
            float wA = evA * sA, wB = evB * sB;  // fold ||h_c|| back in

            aa.x = fmaf(wA, yaA.x, aa.x);  aa.x = fmaf(wB, yaB.x, aa.x);
            aa.y = fmaf(wA, yaA.y, aa.y);  aa.y = fmaf(wB, yaB.y, aa.y);
            aa.z = fmaf(wA, yaA.z, aa.z);  aa.z = fmaf(wB, yaB.z, aa.z);
            aa.w = fmaf(wA, yaA.w, aa.w);  aa.w = fmaf(wB, yaB.w, aa.w);
            ab.x = fmaf(wA, ybA.x, ab.x);  ab.x = fmaf(wB, ybB.x, ab.x);
            ab.y = fmaf(wA, ybA.y, ab.y);  ab.y = fmaf(wB, ybB.y, ab.y);
            ab.z = fmaf(wA, ybA.z, ab.z);  ab.z = fmaf(wB, ybB.z, ab.z);
            ab.w = fmaf(wA, ybA.w, ab.w);  ab.w = fmaf(wB, ybB.w, ab.w);

            cA = ncA; cB = ncB; sA = nsA; sB = nsB;
        }

        // merge the 4 quarter-accumulators (butterfly across lanes 8, 16)
#pragma unroll
        for (int m = 8; m <= 16; m <<= 1) {
            ws   += __shfl_xor_sync(0xffffffffu, ws, m);
            aa.x += __shfl_xor_sync(0xffffffffu, aa.x, m);
            aa.y += __shfl_xor_sync(0xffffffffu, aa.y, m);
            aa.z += __shfl_xor_sync(0xffffffffu, aa.z, m);
            aa.w += __shfl_xor_sync(0xffffffffu, aa.w, m);
            ab.x += __shfl_xor_sync(0xffffffffu, ab.x, m);
            ab.y += __shfl_xor_sync(0xffffffffu, ab.y, m);
            ab.z += __shfl_xor_sync(0xffffffffu, ab.z, m);
            ab.w += __shfl_xor_sync(0xffffffffu, ab.w, m);
        }

        float inv = 1.0f / fmaxf(ws, 1e-12f);
        float4 oa, ob;
        oa.x = fmaxf(aa.x * inv, 0.f);
        oa.y = fmaxf(aa.y * inv, 0.f);
        oa.z = fmaxf(aa.z * inv, 0.f);
        oa.w = fmaxf(aa.w * inv, 0.f);
        ob.x = fmaxf(ab.x * inv, 0.f);
        ob.y = fmaxf(ab.y * inv, 0.f);
        ob.z = fmaxf(ab.z * inv, 0.f);
        ob.w = fmaxf(ab.w * inv, 0.f);

        if (LAST) {
            if (q == 0) {
                ((float4*)g_h)[node * 16 + lq]     = oa;
                ((float4*)g_h)[node * 16 + 8 + lq] = ob;
            }
        } else {
            // fused normalize for the next layer
            float pp = oa.x * oa.x;
            pp = fmaf(oa.y, oa.y, pp);
            pp = fmaf(oa.z, oa.z, pp);
            pp = fmaf(oa.w, oa.w, pp);
            pp = fmaf(ob.x, ob.x, pp);
            pp = fmaf(ob.y, ob.y, pp);
            pp = fmaf(ob.z, ob.z, pp);
            pp = fmaf(ob.w, ob.w, pp);
            pp += __shfl_xor_sync(0xffffffffu, pp, 1);
            pp += __shfl_xor_sync(0xffffffffu, pp, 2);
            pp += __shfl_xor_sync(0xffffffffu, pp, 4);
            float nrm = sqrtf(pp) + 1e-12f;
            float iv = 1.0f / nrm;
            if (q == 0) {
                ((float4*)g_xn[dst])[node * 16 + lq] =
                    make_float4(oa.x * iv, oa.y * iv, oa.z * iv, oa.w * iv);
                ((float4*)g_xn[dst])[node * 16 + 8 + lq] =
                    make_float4(ob.x * iv, ob.y * iv, ob.z * iv, ob.w * iv);
                if (lq == 0) g_s[dst][node] = nrm;
            }
        }
    }
}

// ---------------------------------------------------------------------------
extern "C" void kernel_launch(void* const* d_in, const int* in_sizes, int n_in,
                              void* d_out, int out_size) {
    const float* x    = (const float*)d_in[0];
    const int*   erow = (const int*)d_in[1];
    const int*   ecol = (const int*)d_in[2];
    const float* W1   = (const float*)d_in[3];
    const float* b1   = (const float*)d_in[4];
    const float* W2   = (const float*)d_in[5];
    const float* b2   = (const float*)d_in[6];

    int N = in_sizes[0] / IN_DIM;
    int E = in_sizes[1];

    rowptr_kernel<<<(N + 1 + 255) / 256, 256>>>(erow, N, E);

    // h0 = relu(x @ W1^T + b1), fused normalize -> g_xn[0], g_s[0]
    gemm_kernel<IN_DIM, true><<<PROP_BLOCKS, 256>>>(x, W1, b1, nullptr, N);

    prop_kernel<false><<<PROP_BLOCKS, 256>>>(ecol, 0, N);
    prop_kernel<false><<<PROP_BLOCKS, 256>>>(ecol, 1, N);
    prop_kernel<false><<<PROP_BLOCKS, 256>>>(ecol, 0, N);
    prop_kernel<true ><<<PROP_BLOCKS, 256>>>(ecol, 1, N);

    // out = g_h @ W2^T + b2
    gemm_kernel<HID, false><<<PROP_BLOCKS, 256>>>(nullptr, W2, b2,
                                                  (float*)d_out, N);
}